// round 3
// baseline (speedup 1.0000x reference)
#include <cuda_runtime.h>
#include <cstdint>

// VectorQuantizer: z[32,64,32,32] fp32, codebook[1024,64] fp32
// out = [ z_q (2097152 f32) | loss (1 f32) | indices (32768 f32) ]

#define C_DIM    64
#define K_CB     1024
#define P_BLK    64
#define K_TILE   128
#define NT       128
#define Z_ELEMS  2097152
#define N_PIX    32768
#define GRID_MAIN (N_PIX / P_BLK)   // 512

// device scratch (no cudaMalloc allowed)
__device__ float    g_Et[C_DIM * K_CB];   // transposed codebook [c][k]
__device__ float    g_e2[K_CB];           // sum(e^2) per code (sequential-c order)
__device__ float    g_z2[N_PIX];          // sum(z^2) per pixel (sequential-c order)
__device__ double   g_sum;                // loss accumulator
__device__ unsigned g_ticket;             // last-block detector

__device__ __forceinline__ unsigned long long pack2dup(float x) {
    unsigned long long r;
    unsigned int u = __float_as_uint(x);
    asm("mov.b64 %0, {%1, %1};" : "=l"(r) : "r"(u));
    return r;
}
__device__ __forceinline__ void fma2(unsigned long long& d,
                                     unsigned long long a,
                                     unsigned long long b) {
    asm("fma.rn.f32x2 %0, %1, %2, %0;" : "+l"(d) : "l"(a), "l"(b));
}
__device__ __forceinline__ float2 unpack2(unsigned long long v) {
    unsigned int a, b;
    asm("mov.b64 {%0, %1}, %2;" : "=r"(a), "=r"(b) : "l"(v));
    return make_float2(__uint_as_float(a), __uint_as_float(b));
}

// ---------------------------------------------------------------------------
// Prep (192 blocks x 256): transpose codebook, e2 (seq c), z2 (seq c), resets.
// ---------------------------------------------------------------------------
__global__ void vq_prep(const float* __restrict__ cb, const float* __restrict__ z) {
    int id = blockIdx.x * blockDim.x + threadIdx.x;
    if (id == 0) { g_sum = 0.0; g_ticket = 0u; }

    if (id < 16384) {            // transpose: id = k*16 + c4chunk
        int k  = id >> 4;
        int c4 = (id & 15) * 4;
        float4 v = *(const float4*)(cb + k * 64 + c4);
        g_Et[(c4 + 0) * 1024 + k] = v.x;
        g_Et[(c4 + 1) * 1024 + k] = v.y;
        g_Et[(c4 + 2) * 1024 + k] = v.z;
        g_Et[(c4 + 3) * 1024 + k] = v.w;
    }
    if (id < 1024) {             // e2: strict sequential over c
        const float* row = cb + id * 64;
        float s = 0.f;
        #pragma unroll
        for (int c = 0; c < 64; c++)
            s = __fadd_rn(s, __fmul_rn(row[c], row[c]));
        g_e2[id] = s;
    }
    if (id >= 16384 && id < 16384 + N_PIX) {   // z2: strict sequential over c
        int n = id - 16384;
        int b = n >> 10, p = n & 1023;
        const float* zp = z + (size_t)b * 65536 + p;
        float s = 0.f;
        #pragma unroll
        for (int c = 0; c < 64; c++) {
            float v = zp[c * 1024];
            s = __fadd_rn(s, __fmul_rn(v, v));
        }
        g_z2[n] = s;
    }
}

// ---------------------------------------------------------------------------
// Main: block = 64 pixels, 128 threads. 8 tiles of 128 codes.
// Thread (tx=tid&15 -> 8 codes as 4 f32x2 pairs, ty=tid>>4 -> 8 pixels).
// Inner step per channel: 6 LDS.128 + 32 FFMA2, zero MOVs.
// d = fl( fl(sz+e2) - 2*dot ) replicates the reference expression tree.
// ---------------------------------------------------------------------------
__global__ __launch_bounds__(NT, 3)
void vq_main(const float* __restrict__ z, float* __restrict__ out) {
    extern __shared__ char smem_raw[];
    unsigned long long* sZd = (unsigned long long*)smem_raw;     // [64][64] dup pairs, 32KB
    float*  sE   = (float*)(sZd + 64 * 64);                      // [64][128] 32KB
    float*  sE2  = sE + 64 * 128;                                // [128]
    int*    sIdx = (int*)(sE2 + 128);                            // [64]
    double* sRed = (double*)(sIdx + 64);                         // [4]

    const int tid = threadIdx.x;
    const int tx  = tid & 15;
    const int ty  = tid >> 4;          // 0..7
    const int pxb = ty * 8;            // 8 pixels per thread
    const int n0  = blockIdx.x * P_BLK;
    const int b   = n0 >> 10;
    const int p0  = n0 & 1023;
    const float* zb = z + (size_t)b * 65536 + p0;

    // load z tile, duplicating each value into an f32x2 pair
    for (int i = tid; i < 64 * 64; i += NT) {
        int c = i >> 6, px = i & 63;
        sZd[c * 64 + px] = pack2dup(zb[c * 1024 + px]);
    }

    float sz[8];
    #pragma unroll
    for (int p = 0; p < 8; p++) sz[p] = g_z2[n0 + pxb + p];

    float best[8]; int bidx[8];
    #pragma unroll
    for (int p = 0; p < 8; p++) { best[p] = 3.4e38f; bidx[p] = 0; }

    for (int t = 0; t < K_CB / K_TILE; t++) {
        __syncthreads();
        // load E tile [64][128]
        for (int i = tid; i < 2048; i += NT) {
            int c = i >> 5, kk = (i & 31) * 4;
            *(float4*)(sE + c * 128 + kk) =
                *(const float4*)(g_Et + c * 1024 + t * 128 + kk);
        }
        sE2[tid] = g_e2[t * 128 + tid];
        __syncthreads();

        unsigned long long acc[8][4];
        #pragma unroll
        for (int p = 0; p < 8; p++)
            #pragma unroll
            for (int q = 0; q < 4; q++) acc[p][q] = 0ull;

        const unsigned long long* zrow = sZd + pxb;
        const float* erow = sE + 4 * tx;

        #pragma unroll 4
        for (int c = 0; c < C_DIM; c++) {
            // 8 pixels (dup pairs): 4 LDS.128, broadcast across tx lanes
            ulonglong2 z01 = *(const ulonglong2*)(zrow + c * 64);
            ulonglong2 z23 = *(const ulonglong2*)(zrow + c * 64 + 2);
            ulonglong2 z45 = *(const ulonglong2*)(zrow + c * 64 + 4);
            ulonglong2 z67 = *(const ulonglong2*)(zrow + c * 64 + 6);
            // 8 codes as 4 natural f32x2 pairs: 2 LDS.128, conflict-free
            ulonglong2 ea = *(const ulonglong2*)(erow + c * 128);
            ulonglong2 eb = *(const ulonglong2*)(erow + c * 128 + 64);
            unsigned long long zp[8] = { z01.x, z01.y, z23.x, z23.y,
                                         z45.x, z45.y, z67.x, z67.y };
            #pragma unroll
            for (int p = 0; p < 8; p++) {
                fma2(acc[p][0], zp[p], ea.x);
                fma2(acc[p][1], zp[p], ea.y);
                fma2(acc[p][2], zp[p], eb.x);
                fma2(acc[p][3], zp[p], eb.y);
            }
        }

        // d = fl(sz+e2) - 2*dot; strict < keeps first (smallest) index
        #pragma unroll
        for (int q = 0; q < 4; q++) {
            int k0 = (q < 2) ? (4 * tx + 2 * q) : (64 + 4 * tx + 2 * (q - 2));
            float e20 = sE2[k0], e21 = sE2[k0 + 1];
            int kg = t * 128 + k0;
            #pragma unroll
            for (int p = 0; p < 8; p++) {
                float2 dp = unpack2(acc[p][q]);
                float d0 = __fmaf_rn(dp.x, -2.f, __fadd_rn(sz[p], e20));
                float d1 = __fmaf_rn(dp.y, -2.f, __fadd_rn(sz[p], e21));
                if (d0 < best[p]) { best[p] = d0; bidx[p] = kg; }
                if (d1 < best[p]) { best[p] = d1; bidx[p] = kg + 1; }
            }
        }
    }

    // argmin reduce across the 16 tx lanes (xor widths stay inside 16-lane halves)
    #pragma unroll
    for (int p = 0; p < 8; p++) {
        float bv = best[p]; int bi = bidx[p];
        #pragma unroll
        for (int off = 8; off >= 1; off >>= 1) {
            float ov = __shfl_xor_sync(0xffffffffu, bv, off);
            int   oi = __shfl_xor_sync(0xffffffffu, bi, off);
            if (ov < bv || (ov == bv && oi < bi)) { bv = ov; bi = oi; }
        }
        if (tx == 0) sIdx[pxb + p] = bi;
    }
    __syncthreads();

    // epilogue: gather, straight-through output, loss partial, indices
    double lsum = 0.0;
    for (int i = tid; i < P_BLK * C_DIM; i += NT) {
        int c = i >> 6, px = i & 63;
        int k = sIdx[px];
        float ev  = g_Et[c * 1024 + k];
        float zv  = __uint_as_float((unsigned)(sZd[c * 64 + px] & 0xffffffffu));
        float tdf = __fadd_rn(ev, -zv);
        out[(size_t)b * 65536 + c * 1024 + p0 + px] = __fadd_rn(zv, tdf);
        lsum += (double)__fmul_rn(tdf, tdf);
    }
    if (tid < P_BLK)
        out[(size_t)Z_ELEMS + 1 + n0 + tid] = (float)sIdx[tid];

    #pragma unroll
    for (int off = 16; off >= 1; off >>= 1)
        lsum += __shfl_down_sync(0xffffffffu, lsum, off);
    if ((tid & 31) == 0) sRed[tid >> 5] = lsum;
    __syncthreads();

    // fused finish: last block writes the loss
    if (tid == 0) {
        double s = sRed[0] + sRed[1] + sRed[2] + sRed[3];
        atomicAdd(&g_sum, s);
        __threadfence();
        unsigned tk = atomicAdd(&g_ticket, 1u);
        if (tk == (unsigned)(gridDim.x - 1)) {
            double tot = atomicAdd(&g_sum, 0.0);
            float mf = (float)(tot / (double)Z_ELEMS);
            out[Z_ELEMS] = __fadd_rn(mf, __fmul_rn(0.25f, mf));
        }
    }
}

extern "C" void kernel_launch(void* const* d_in, const int* in_sizes, int n_in,
                              void* d_out, int out_size) {
    const float* z  = (const float*)d_in[0];
    const float* cb = (const float*)d_in[1];
    float* out = (float*)d_out;

    const int smem_bytes = 64 * 64 * 8 + 64 * 128 * 4 + 128 * 4 + 64 * 4 + 4 * 8;
    cudaFuncSetAttribute(vq_main, cudaFuncAttributeMaxDynamicSharedMemorySize,
                         smem_bytes);

    vq_prep<<<192, 256>>>(cb, z);
    vq_main<<<GRID_MAIN, NT, smem_bytes>>>(z, out);
}

// round 4
// speedup vs baseline: 1.0147x; 1.0147x over previous
#include <cuda_runtime.h>
#include <cstdint>

// VectorQuantizer: z[32,64,32,32] fp32, codebook[1024,64] fp32
// out = [ z_q (2097152 f32) | loss (1 f32) | indices (32768 f32) ]

#define C_DIM    64
#define K_CB     1024
#define P_BLK    64
#define K_TILE   128
#define NT       256
#define Z_ELEMS  2097152
#define N_PIX    32768
#define GRID_MAIN (N_PIX / P_BLK)   // 512
#define NTILES   (K_CB / K_TILE)    // 8

// device scratch (no cudaMalloc allowed)
__device__ float    g_Et[C_DIM * K_CB];   // transposed codebook [c][k]
__device__ float    g_e2[K_CB];           // sum(e^2) per code (sequential-c order)
__device__ float    g_z2[N_PIX];          // sum(z^2) per pixel (sequential-c order)
__device__ double   g_sum;                // loss accumulator
__device__ unsigned g_ticket;             // last-block detector

__device__ __forceinline__ unsigned long long pack2dup(float x) {
    unsigned long long r;
    unsigned int u = __float_as_uint(x);
    asm("mov.b64 %0, {%1, %1};" : "=l"(r) : "r"(u));
    return r;
}
__device__ __forceinline__ void fma2(unsigned long long& d,
                                     unsigned long long a,
                                     unsigned long long b) {
    asm("fma.rn.f32x2 %0, %1, %2, %0;" : "+l"(d) : "l"(a), "l"(b));
}
__device__ __forceinline__ float2 unpack2(unsigned long long v) {
    unsigned int a, b;
    asm("mov.b64 {%0, %1}, %2;" : "=r"(a), "=r"(b) : "l"(v));
    return make_float2(__uint_as_float(a), __uint_as_float(b));
}
__device__ __forceinline__ void cp16(unsigned s, const void* g) {
    asm volatile("cp.async.ca.shared.global [%0], [%1], 16;\n"
                 :: "r"(s), "l"(g));
}
__device__ __forceinline__ void cp_commit() {
    asm volatile("cp.async.commit_group;\n");
}
__device__ __forceinline__ void cp_wait0() {
    asm volatile("cp.async.wait_group 0;\n");
}

// ---------------------------------------------------------------------------
// Prep (192 blocks x 256): transpose codebook, e2 (seq c), z2 (seq c), resets.
// ---------------------------------------------------------------------------
__global__ void vq_prep(const float* __restrict__ cb, const float* __restrict__ z) {
    int id = blockIdx.x * blockDim.x + threadIdx.x;
    if (id == 0) { g_sum = 0.0; g_ticket = 0u; }

    if (id < 16384) {            // transpose: id = k*16 + c4chunk
        int k  = id >> 4;
        int c4 = (id & 15) * 4;
        float4 v = *(const float4*)(cb + k * 64 + c4);
        g_Et[(c4 + 0) * 1024 + k] = v.x;
        g_Et[(c4 + 1) * 1024 + k] = v.y;
        g_Et[(c4 + 2) * 1024 + k] = v.z;
        g_Et[(c4 + 3) * 1024 + k] = v.w;
    }
    if (id < 1024) {             // e2: strict sequential over c
        const float* row = cb + id * 64;
        float s = 0.f;
        #pragma unroll
        for (int c = 0; c < 64; c++)
            s = __fadd_rn(s, __fmul_rn(row[c], row[c]));
        g_e2[id] = s;
    }
    if (id >= 16384 && id < 16384 + N_PIX) {   // z2: strict sequential over c
        int n = id - 16384;
        int b = n >> 10, p = n & 1023;
        const float* zp = z + (size_t)b * 65536 + p;
        float s = 0.f;
        #pragma unroll
        for (int c = 0; c < 64; c++) {
            float v = zp[c * 1024];
            s = __fadd_rn(s, __fmul_rn(v, v));
        }
        g_z2[n] = s;
    }
}

// ---------------------------------------------------------------------------
// Main: block = 64 pixels, 256 threads. 8 tiles of 128 codes,
// cp.async double-buffered (E-tile load latency fully hidden).
// Thread (tx=tid&15 -> 8 codes as 4 f32x2 pairs, ty=tid>>4 -> 4 pixels).
// Inner step per channel: 4 LDS.128 + 16 FFMA2, zero MOVs.
// d = fl( fl(sz+e2) - 2*dot ) replicates the reference expression tree.
// ---------------------------------------------------------------------------
__global__ __launch_bounds__(NT, 2)
void vq_main(const float* __restrict__ z, float* __restrict__ out) {
    extern __shared__ char smem_raw[];
    unsigned long long* sZd = (unsigned long long*)smem_raw;     // [64][64] dup pairs 32KB
    float*  sE   = (float*)(sZd + 64 * 64);                      // [2][64][128] 64KB
    int*    sIdx = (int*)(sE + 2 * 64 * 128);                    // [64]
    double* sRed = (double*)(sIdx + 64);                         // [8]

    const int tid = threadIdx.x;
    const int tx  = tid & 15;
    const int ty  = tid >> 4;          // 0..15
    const int pxb = ty * 4;            // 4 pixels per thread
    const int n0  = blockIdx.x * P_BLK;
    const int b   = n0 >> 10;
    const int p0  = n0 & 1023;
    const float* zb = z + (size_t)b * 65536 + p0;

    const unsigned sE_base = (unsigned)__cvta_generic_to_shared(sE);

    // kick off prefetch of E tile 0 into buffer 0 (8 x 16B per thread)
    {
        #pragma unroll
        for (int j = 0; j < 8; j++) {
            int f  = tid + j * NT;             // float4 index in tile
            int c  = f >> 5;
            int k4 = (f & 31) << 2;
            cp16(sE_base + (unsigned)(c * 128 + k4) * 4u,
                 g_Et + c * 1024 + k4);
        }
        cp_commit();
    }

    // load z tile, duplicating each value into an f32x2 pair
    for (int i = tid; i < 64 * 64; i += NT) {
        int c = i >> 6, px = i & 63;
        sZd[c * 64 + px] = pack2dup(zb[c * 1024 + px]);
    }

    float sz[4];
    #pragma unroll
    for (int p = 0; p < 4; p++) sz[p] = g_z2[n0 + pxb + p];

    float best[4]; int bidx[4];
    #pragma unroll
    for (int p = 0; p < 4; p++) { best[p] = 3.4e38f; bidx[p] = 0; }

    for (int t = 0; t < NTILES; t++) {
        cp_wait0();
        __syncthreads();    // tile t resident in buf (t&1); prior compute done

        if (t + 1 < NTILES) {   // prefetch tile t+1 into the other buffer
            unsigned dstb = sE_base + (unsigned)(((t + 1) & 1) * 8192) * 4u;
            const float* srcb = g_Et + (t + 1) * 128;
            #pragma unroll
            for (int j = 0; j < 8; j++) {
                int f  = tid + j * NT;
                int c  = f >> 5;
                int k4 = (f & 31) << 2;
                cp16(dstb + (unsigned)(c * 128 + k4) * 4u,
                     srcb + c * 1024 + k4);
            }
            cp_commit();
        }

        // prefetch e2 for my 8 codes (hidden under the FMA loop)
        float4 e2a = *(const float4*)(g_e2 + t * 128 + 4 * tx);
        float4 e2b = *(const float4*)(g_e2 + t * 128 + 64 + 4 * tx);

        unsigned long long acc[4][4];
        #pragma unroll
        for (int p = 0; p < 4; p++)
            #pragma unroll
            for (int q = 0; q < 4; q++) acc[p][q] = 0ull;

        const unsigned long long* zrow = sZd + pxb;
        const float* erow = sE + (t & 1) * 8192 + 4 * tx;

        #pragma unroll 8
        for (int c = 0; c < C_DIM; c++) {
            ulonglong2 za = *(const ulonglong2*)(zrow + c * 64);
            ulonglong2 zc = *(const ulonglong2*)(zrow + c * 64 + 2);
            ulonglong2 ea = *(const ulonglong2*)(erow + c * 128);
            ulonglong2 eb = *(const ulonglong2*)(erow + c * 128 + 64);
            unsigned long long zp[4] = { za.x, za.y, zc.x, zc.y };
            #pragma unroll
            for (int p = 0; p < 4; p++) {
                fma2(acc[p][0], zp[p], ea.x);
                fma2(acc[p][1], zp[p], ea.y);
                fma2(acc[p][2], zp[p], eb.x);
                fma2(acc[p][3], zp[p], eb.y);
            }
        }

        // d = fl(sz+e2) - 2*dot; strict < keeps first (smallest) index
        float e2v[8] = { e2a.x, e2a.y, e2a.z, e2a.w,
                         e2b.x, e2b.y, e2b.z, e2b.w };
        #pragma unroll
        for (int q = 0; q < 4; q++) {
            int k0 = (q < 2) ? (4 * tx + 2 * q) : (64 + 4 * tx + 2 * (q - 2));
            float e20 = e2v[2 * q], e21 = e2v[2 * q + 1];
            int kg = t * 128 + k0;
            #pragma unroll
            for (int p = 0; p < 4; p++) {
                float2 dp = unpack2(acc[p][q]);
                float d0 = __fmaf_rn(dp.x, -2.f, __fadd_rn(sz[p], e20));
                float d1 = __fmaf_rn(dp.y, -2.f, __fadd_rn(sz[p], e21));
                if (d0 < best[p]) { best[p] = d0; bidx[p] = kg; }
                if (d1 < best[p]) { best[p] = d1; bidx[p] = kg + 1; }
            }
        }
    }

    // argmin reduce across the 16 tx lanes (xor widths stay inside 16-lane halves)
    #pragma unroll
    for (int p = 0; p < 4; p++) {
        float bv = best[p]; int bi = bidx[p];
        #pragma unroll
        for (int off = 8; off >= 1; off >>= 1) {
            float ov = __shfl_xor_sync(0xffffffffu, bv, off);
            int   oi = __shfl_xor_sync(0xffffffffu, bi, off);
            if (ov < bv || (ov == bv && oi < bi)) { bv = ov; bi = oi; }
        }
        if (tx == 0) sIdx[pxb + p] = bi;
    }
    __syncthreads();

    // epilogue: gather, straight-through output, loss partial, indices
    double lsum = 0.0;
    for (int i = tid; i < P_BLK * C_DIM; i += NT) {
        int c = i >> 6, px = i & 63;
        int k = sIdx[px];
        float ev  = g_Et[c * 1024 + k];
        float zv  = __uint_as_float((unsigned)(sZd[c * 64 + px] & 0xffffffffu));
        float tdf = __fadd_rn(ev, -zv);
        out[(size_t)b * 65536 + c * 1024 + p0 + px] = __fadd_rn(zv, tdf);
        lsum += (double)__fmul_rn(tdf, tdf);
    }
    if (tid < P_BLK)
        out[(size_t)Z_ELEMS + 1 + n0 + tid] = (float)sIdx[tid];

    #pragma unroll
    for (int off = 16; off >= 1; off >>= 1)
        lsum += __shfl_down_sync(0xffffffffu, lsum, off);
    if ((tid & 31) == 0) sRed[tid >> 5] = lsum;
    __syncthreads();

    // fused finish: last block writes the loss
    if (tid == 0) {
        double s = 0.0;
        #pragma unroll
        for (int w = 0; w < 8; w++) s += sRed[w];
        atomicAdd(&g_sum, s);
        __threadfence();
        unsigned tk = atomicAdd(&g_ticket, 1u);
        if (tk == (unsigned)(gridDim.x - 1)) {
            double tot = atomicAdd(&g_sum, 0.0);
            float mf = (float)(tot / (double)Z_ELEMS);
            out[Z_ELEMS] = __fadd_rn(mf, __fmul_rn(0.25f, mf));
        }
    }
}

extern "C" void kernel_launch(void* const* d_in, const int* in_sizes, int n_in,
                              void* d_out, int out_size) {
    const float* z  = (const float*)d_in[0];
    const float* cb = (const float*)d_in[1];
    float* out = (float*)d_out;

    const int smem_bytes = 64 * 64 * 8 + 2 * 64 * 128 * 4 + 64 * 4 + 8 * 8;
    cudaFuncSetAttribute(vq_main, cudaFuncAttributeMaxDynamicSharedMemorySize,
                         smem_bytes);

    vq_prep<<<192, 256>>>(cb, z);
    vq_main<<<GRID_MAIN, NT, smem_bytes>>>(z, out);
}

// round 7
// speedup vs baseline: 1.1673x; 1.1505x over previous
#include <cuda_runtime.h>
#include <cstdint>

// VectorQuantizer: z[32,64,32,32] fp32, codebook[1024,64] fp32
// out = [ z_q (2097152 f32) | loss (1 f32) | indices (32768 f32) ]

#define C_DIM    64
#define K_CB     1024
#define P_BLK    64
#define K_TILE   128
#define NT       128
#define Z_ELEMS  2097152
#define N_PIX    32768
#define GRID_MAIN (N_PIX / P_BLK)   // 512
#define NTILES   (K_CB / K_TILE)    // 8

__device__ float    g_Et[C_DIM * K_CB];   // transposed codebook [c][k]
__device__ float    g_e2[K_CB];           // sum(e^2) per code (sequential-c order)
__device__ float    g_z2[N_PIX];          // sum(z^2) per pixel (sequential-c order)
__device__ double   g_sum;
__device__ unsigned g_ticket;

__device__ __forceinline__ unsigned long long pack2dup(float x) {
    unsigned long long r;
    unsigned int u = __float_as_uint(x);
    asm("mov.b64 %0, {%1, %1};" : "=l"(r) : "r"(u));
    return r;
}
__device__ __forceinline__ void fma2(unsigned long long& d,
                                     unsigned long long a,
                                     unsigned long long b) {
    asm("fma.rn.f32x2 %0, %1, %2, %0;" : "+l"(d) : "l"(a), "l"(b));
}
__device__ __forceinline__ float2 unpack2(unsigned long long v) {
    unsigned int a, b;
    asm("mov.b64 {%0, %1}, %2;" : "=r"(a), "=r"(b) : "l"(v));
    return make_float2(__uint_as_float(a), __uint_as_float(b));
}
__device__ __forceinline__ void cp16(unsigned s, const void* g) {
    asm volatile("cp.async.ca.shared.global [%0], [%1], 16;\n" :: "r"(s), "l"(g));
}
__device__ __forceinline__ void cp_commit() {
    asm volatile("cp.async.commit_group;\n");
}
__device__ __forceinline__ void cp_wait0() {
    asm volatile("cp.async.wait_group 0;\n");
}

// ---------------------------------------------------------------------------
__global__ void vq_prep(const float* __restrict__ cb, const float* __restrict__ z) {
    int id = blockIdx.x * blockDim.x + threadIdx.x;
    if (id == 0) { g_sum = 0.0; g_ticket = 0u; }

    if (id < 16384) {            // transpose
        int k  = id >> 4;
        int c4 = (id & 15) * 4;
        float4 v = *(const float4*)(cb + k * 64 + c4);
        g_Et[(c4 + 0) * 1024 + k] = v.x;
        g_Et[(c4 + 1) * 1024 + k] = v.y;
        g_Et[(c4 + 2) * 1024 + k] = v.z;
        g_Et[(c4 + 3) * 1024 + k] = v.w;
    }
    if (id < 1024) {             // e2: strict sequential over c
        const float* row = cb + id * 64;
        float s = 0.f;
        #pragma unroll
        for (int c = 0; c < 64; c++)
            s = __fadd_rn(s, __fmul_rn(row[c], row[c]));
        g_e2[id] = s;
    }
    if (id >= 16384 && id < 16384 + N_PIX) {   // z2: strict sequential over c
        int n = id - 16384;
        int b = n >> 10, p = n & 1023;
        const float* zp = z + (size_t)b * 65536 + p;
        float s = 0.f;
        #pragma unroll
        for (int c = 0; c < 64; c++) {
            float v = zp[c * 1024];
            s = __fadd_rn(s, __fmul_rn(v, v));
        }
        g_z2[n] = s;
    }
}

// ---------------------------------------------------------------------------
// Main: 128 threads, 64 pixels/block, 8 K-tiles of 128 codes (cp.async dbuf).
// Thread (tx=tid&15 -> 8 codes, ty=tid>>4 -> 8 pixels), 8x8 register tile.
// Explicit SW pipeline: channel c+1's z/e prefetched into regs before c's FMAs
// so the LDS(29cy) latency is covered by 32 FFMA2 issues.
// d = fl( fl(sz+e2) - 2*dot ) replicates the reference expression tree.
// ---------------------------------------------------------------------------
__global__ __launch_bounds__(NT, 2)
void vq_main(const float* __restrict__ z, float* __restrict__ out) {
    extern __shared__ char smem_raw[];
    unsigned long long* sZd = (unsigned long long*)smem_raw;     // [64][64] dup, 32KB
    float*  sE   = (float*)(sZd + 64 * 64);                      // [2][64][128] 64KB
    int*    sIdx = (int*)(sE + 2 * 64 * 128);                    // [64]
    double* sRed = (double*)(sIdx + 64);                         // [4]

    const int tid = threadIdx.x;
    const int tx  = tid & 15;
    const int ty  = tid >> 4;          // 0..7
    const int pxb = ty * 8;            // 8 pixels per thread
    const int n0  = blockIdx.x * P_BLK;
    const int b   = n0 >> 10;
    const int p0  = n0 & 1023;
    const float* zb = z + (size_t)b * 65536 + p0;

    const unsigned sE_base = (unsigned)__cvta_generic_to_shared(sE);

    // prefetch E tile 0 into buffer 0 (16 x 16B per thread)
    #pragma unroll
    for (int j = 0; j < 16; j++) {
        int f  = tid + j * NT;
        int c  = f >> 5;
        int k4 = (f & 31) << 2;
        cp16(sE_base + (unsigned)(c * 128 + k4) * 4u, g_Et + c * 1024 + k4);
    }
    cp_commit();

    // load z tile, duplicating each value into an f32x2 pair
    for (int i = tid; i < 64 * 64; i += NT) {
        int c = i >> 6, px = i & 63;
        sZd[c * 64 + px] = pack2dup(zb[c * 1024 + px]);
    }

    float sz[8];
    #pragma unroll
    for (int p = 0; p < 8; p++) sz[p] = g_z2[n0 + pxb + p];

    float best[8]; int bidx[8];
    #pragma unroll
    for (int p = 0; p < 8; p++) { best[p] = 3.4e38f; bidx[p] = 0; }

    for (int t = 0; t < NTILES; t++) {
        cp_wait0();
        __syncthreads();    // tile t resident; previous compute finished

        if (t + 1 < NTILES) {   // prefetch next tile into other buffer
            unsigned dstb = sE_base + (unsigned)(((t + 1) & 1) * 8192) * 4u;
            const float* srcb = g_Et + (t + 1) * 128;
            #pragma unroll
            for (int j = 0; j < 16; j++) {
                int f  = tid + j * NT;
                int c  = f >> 5;
                int k4 = (f & 31) << 2;
                cp16(dstb + (unsigned)(c * 128 + k4) * 4u, srcb + c * 1024 + k4);
            }
            cp_commit();
        }

        float4 e2a = *(const float4*)(g_e2 + t * 128 + 4 * tx);
        float4 e2b = *(const float4*)(g_e2 + t * 128 + 64 + 4 * tx);

        unsigned long long acc[8][4];
        #pragma unroll
        for (int p = 0; p < 8; p++)
            #pragma unroll
            for (int q = 0; q < 4; q++) acc[p][q] = 0ull;

        const unsigned long long* zrow = sZd + pxb;
        const float* erow = sE + (t & 1) * 8192 + 4 * tx;

        // ---- software-pipelined mainloop over channels ----
        ulonglong2 zr[2][4];   // [stage][4 x ull2 = 8 dup pixels]
        ulonglong2 er[2][2];   // [stage][2 x ull2 = 8 codes]

        zr[0][0] = *(const ulonglong2*)(zrow);
        zr[0][1] = *(const ulonglong2*)(zrow + 2);
        zr[0][2] = *(const ulonglong2*)(zrow + 4);
        zr[0][3] = *(const ulonglong2*)(zrow + 6);
        er[0][0] = *(const ulonglong2*)(erow);
        er[0][1] = *(const ulonglong2*)(erow + 64);

        #pragma unroll 8
        for (int c = 0; c < C_DIM; c++) {
            const int cur = c & 1, nxt = cur ^ 1;
            const int nc  = (c + 1) & 63;          // in-bounds dummy at c=63
            // prefetch channel c+1 (consumed 32 FFMA2 issues later)
            zr[nxt][0] = *(const ulonglong2*)(zrow + nc * 64);
            zr[nxt][1] = *(const ulonglong2*)(zrow + nc * 64 + 2);
            zr[nxt][2] = *(const ulonglong2*)(zrow + nc * 64 + 4);
            zr[nxt][3] = *(const ulonglong2*)(zrow + nc * 64 + 6);
            er[nxt][0] = *(const ulonglong2*)(erow + nc * 128);
            er[nxt][1] = *(const ulonglong2*)(erow + nc * 128 + 64);

            unsigned long long e0 = er[cur][0].x, e1 = er[cur][0].y;
            unsigned long long e2 = er[cur][1].x, e3 = er[cur][1].y;
            unsigned long long zp[8] = { zr[cur][0].x, zr[cur][0].y,
                                         zr[cur][1].x, zr[cur][1].y,
                                         zr[cur][2].x, zr[cur][2].y,
                                         zr[cur][3].x, zr[cur][3].y };
            #pragma unroll
            for (int p = 0; p < 8; p++) {
                fma2(acc[p][0], zp[p], e0);
                fma2(acc[p][1], zp[p], e1);
                fma2(acc[p][2], zp[p], e2);
                fma2(acc[p][3], zp[p], e3);
            }
        }

        // d = fl(sz+e2) - 2*dot; strict < keeps first (smallest) index
        float e2v[8] = { e2a.x, e2a.y, e2a.z, e2a.w,
                         e2b.x, e2b.y, e2b.z, e2b.w };
        #pragma unroll
        for (int q = 0; q < 4; q++) {
            int k0 = (q < 2) ? (4 * tx + 2 * q) : (64 + 4 * tx + 2 * (q - 2));
            float e20 = e2v[2 * q], e21 = e2v[2 * q + 1];
            int kg = t * 128 + k0;
            #pragma unroll
            for (int p = 0; p < 8; p++) {
                float2 dp = unpack2(acc[p][q]);
                float d0 = __fmaf_rn(dp.x, -2.f, __fadd_rn(sz[p], e20));
                float d1 = __fmaf_rn(dp.y, -2.f, __fadd_rn(sz[p], e21));
                if (d0 < best[p]) { best[p] = d0; bidx[p] = kg; }
                if (d1 < best[p]) { best[p] = d1; bidx[p] = kg + 1; }
            }
        }
    }

    // argmin reduce across the 16 tx lanes
    #pragma unroll
    for (int p = 0; p < 8; p++) {
        float bv = best[p]; int bi = bidx[p];
        #pragma unroll
        for (int off = 8; off >= 1; off >>= 1) {
            float ov = __shfl_xor_sync(0xffffffffu, bv, off);
            int   oi = __shfl_xor_sync(0xffffffffu, bi, off);
            if (ov < bv || (ov == bv && oi < bi)) { bv = ov; bi = oi; }
        }
        if (tx == 0) sIdx[pxb + p] = bi;
    }
    __syncthreads();

    // epilogue: gather, straight-through output, loss partial, indices
    double lsum = 0.0;
    for (int i = tid; i < P_BLK * C_DIM; i += NT) {
        int c = i >> 6, px = i & 63;
        int k = sIdx[px];
        float ev  = g_Et[c * 1024 + k];
        float zv  = __uint_as_float((unsigned)(sZd[c * 64 + px] & 0xffffffffu));
        float tdf = __fadd_rn(ev, -zv);
        out[(size_t)b * 65536 + c * 1024 + p0 + px] = __fadd_rn(zv, tdf);
        lsum += (double)__fmul_rn(tdf, tdf);
    }
    if (tid < P_BLK)
        out[(size_t)Z_ELEMS + 1 + n0 + tid] = (float)sIdx[tid];

    #pragma unroll
    for (int off = 16; off >= 1; off >>= 1)
        lsum += __shfl_down_sync(0xffffffffu, lsum, off);
    if ((tid & 31) == 0) sRed[tid >> 5] = lsum;
    __syncthreads();

    if (tid == 0) {
        double s = sRed[0] + sRed[1] + sRed[2] + sRed[3];
        atomicAdd(&g_sum, s);
        __threadfence();
        unsigned tk = atomicAdd(&g_ticket, 1u);
        if (tk == (unsigned)(gridDim.x - 1)) {
            double tot = atomicAdd(&g_sum, 0.0);
            float mf = (float)(tot / (double)Z_ELEMS);
            out[Z_ELEMS] = __fadd_rn(mf, __fmul_rn(0.25f, mf));
        }
    }
}

extern "C" void kernel_launch(void* const* d_in, const int* in_sizes, int n_in,
                              void* d_out, int out_size) {
    const float* z  = (const float*)d_in[0];
    const float* cb = (const float*)d_in[1];
    float* out = (float*)d_out;

    const int smem_bytes = 64 * 64 * 8 + 2 * 64 * 128 * 4 + 64 * 4 + 4 * 8;
    cudaFuncSetAttribute(vq_main, cudaFuncAttributeMaxDynamicSharedMemorySize,
                         smem_bytes);

    vq_prep<<<192, 256>>>(cb, z);
    vq_main<<<GRID_MAIN, NT, smem_bytes>>>(z, out);
}